// round 4
// baseline (speedup 1.0000x reference)
#include <cuda_runtime.h>
#include <cuda_bf16.h>

#define NN 100000
#define EE 1600000
#define DD 64
#define NB_SCAN 98          // ceil(NN/1024)
#define PAD 68              // row stride (words) for shared Z/Y1 tiles (16B-aligned rows)

// ---------------- persistent device scratch (no allocations allowed) ----------------
__device__ float g_h0[NN * DD];
__device__ float g_h1[NN * DD];
__device__ int   g_deg[NN];
__device__ int   g_off[NN + 1];
__device__ int   g_cur[NN];
__device__ int   g_srcs[EE];
__device__ int   g_bsum[NB_SCAN];

// ---------------- CSR build ----------------
__global__ void k_zero_deg() {
    int i = blockIdx.x * 256 + threadIdx.x;
    if (i < NN) g_deg[i] = 0;
}

// edge_index is int32 (JAX x64 disabled demotes the reference's int64 to int32):
// row 0 = src (ei[e]), row 1 = dst (ei[EE + e]).
__global__ void k_hist(const int* __restrict__ ei) {
    int e = blockIdx.x * 256 + threadIdx.x;
    if (e < EE) {
        int d = ei[EE + e];
        if (d >= 0 && d < NN) atomicAdd(&g_deg[d], 1);
    }
}

__global__ void k_scan1() {
    __shared__ int sh[1024];
    int t = threadIdx.x;
    int i = blockIdx.x * 1024 + t;
    int v = (i < NN) ? g_deg[i] : 0;
    sh[t] = v;
    __syncthreads();
    for (int d = 1; d < 1024; d <<= 1) {
        int a = (t >= d) ? sh[t - d] : 0;
        __syncthreads();
        sh[t] += a;
        __syncthreads();
    }
    if (i < NN) g_off[i] = sh[t] - v;          // exclusive prefix within block
    if (t == 1023) g_bsum[blockIdx.x] = sh[1023];
}

__global__ void k_scan2() {                      // 1 thread: scan 98 block sums
    int acc = 0;
    for (int b = 0; b < NB_SCAN; b++) { int t = g_bsum[b]; g_bsum[b] = acc; acc += t; }
}

__global__ void k_scanadd() {
    int i = blockIdx.x * 256 + threadIdx.x;
    if (i < NN) {
        int v = g_off[i] + g_bsum[i >> 10];
        g_off[i] = v;
        g_cur[i] = v;
    }
    if (i == 0) g_off[NN] = EE;
}

__global__ void k_scatter(const int* __restrict__ ei) {
    int e = blockIdx.x * 256 + threadIdx.x;
    if (e < EE) {
        int d = ei[EE + e];
        int s = ei[e];
        if (d >= 0 && d < NN && s >= 0 && s < NN) {
            int p = atomicAdd(&g_cur[d], 1);
            if (p < EE) g_srcs[p] = s;
        }
    }
}

// Sort each node's src list so float accumulation order is deterministic across replays.
__global__ void k_segsort() {
    int n = blockIdx.x * 256 + threadIdx.x;
    if (n >= NN) return;
    int a = g_off[n], b = g_off[n + 1];
    for (int i = a + 1; i < b; i++) {
        int key = g_srcs[i];
        int j = i - 1;
        while (j >= a && g_srcs[j] > key) { g_srcs[j + 1] = g_srcs[j]; j--; }
        g_srcs[j + 1] = key;
    }
}

// ---------------- fused GIN layer: aggregate + MLP(64x64x2) + BN + ReLU ----------------
// Block: 256 threads, handles 64 nodes. Shared: Zt (feature-major z, reused as Y1
// row-major), Ws (W1 then reloaded with W2), small bias/BN vectors.
__global__ void __launch_bounds__(256) k_layer(
    const float* __restrict__ x, float* __restrict__ dout,
    const float* __restrict__ W1, const float* __restrict__ b1,
    const float* __restrict__ W2, const float* __restrict__ b2,
    const float* __restrict__ bng, const float* __restrict__ bnb,
    const float* __restrict__ bnm, const float* __restrict__ bnv,
    int layer)
{
    __shared__ __align__(16) float Zt[64 * PAD];   // phase1: Zt[feat][node]; phase2: Y1[node][feat]
    __shared__ __align__(16) float Ws[64 * 64];
    __shared__ float bias1[64], bias2[64], bnsc[64], bnsh[64];

    const float* hin  = (layer == 0) ? x    : ((layer & 1) ? g_h0 : g_h1);
    float*       hout = (layer == 4) ? dout : ((layer & 1) ? g_h1 : g_h0);

    const float* W1p = W1 + layer * 4096;
    const float* W2p = W2 + layer * 4096;

    int tid = threadIdx.x;

    for (int i = tid; i < 4096; i += 256) Ws[i] = W1p[i];
    if (tid < 64) {
        bias1[tid] = b1[layer * 64 + tid];
        bias2[tid] = b2[layer * 64 + tid];
        if (layer < 4) {
            float sc  = bng[layer * 64 + tid] * rsqrtf(bnv[layer * 64 + tid] + 1e-5f);
            bnsc[tid] = sc;
            bnsh[tid] = bnb[layer * 64 + tid] - bnm[layer * 64 + tid] * sc;
        }
    }

    // ---- aggregation: warp per node, z = h[n] + sum_{s in N(n)} h[s] ----
    int w = tid >> 5, l = tid & 31;
    int base = blockIdx.x * 64;
    for (int r = w; r < 64; r += 8) {
        int n = base + r;
        float a0 = 0.f, a1 = 0.f;
        if (n < NN) {
            a0 = hin[n * 64 + l];
            a1 = hin[n * 64 + 32 + l];
            int s0 = g_off[n], s1 = g_off[n + 1];
            #pragma unroll 4
            for (int j = s0; j < s1; j++) {
                int s = g_srcs[j];
                a0 += __ldg(&hin[s * 64 + l]);
                a1 += __ldg(&hin[s * 64 + 32 + l]);
            }
        }
        Zt[l * PAD + r]        = a0;   // z transposed: Zt[feat][node]
        Zt[(l + 32) * PAD + r] = a1;
    }
    __syncthreads();

    // ---- GEMM1: Y1 = relu(Z @ W1 + b1) ----
    int tx = tid & 15, ty = tid >> 4;            // 16x16 thread tile, 4x4 regs each
    float acc[4][4];
    #pragma unroll
    for (int i = 0; i < 4; i++)
        #pragma unroll
        for (int j = 0; j < 4; j++) acc[i][j] = 0.f;

    #pragma unroll 8
    for (int k = 0; k < 64; k++) {
        float4 a = *(const float4*)(Zt + k * PAD + 4 * ty);   // rows 4ty..4ty+3, feat k
        float4 b = *(const float4*)(Ws + k * 64 + 4 * tx);    // feat k, cols 4tx..4tx+3
        acc[0][0] += a.x * b.x; acc[0][1] += a.x * b.y; acc[0][2] += a.x * b.z; acc[0][3] += a.x * b.w;
        acc[1][0] += a.y * b.x; acc[1][1] += a.y * b.y; acc[1][2] += a.y * b.z; acc[1][3] += a.y * b.w;
        acc[2][0] += a.z * b.x; acc[2][1] += a.z * b.y; acc[2][2] += a.z * b.z; acc[2][3] += a.z * b.w;
        acc[3][0] += a.w * b.x; acc[3][1] += a.w * b.y; acc[3][2] += a.w * b.z; acc[3][3] += a.w * b.w;
    }

    float y[4][4];
    #pragma unroll
    for (int i = 0; i < 4; i++)
        #pragma unroll
        for (int j = 0; j < 4; j++)
            y[i][j] = fmaxf(acc[i][j] + bias1[4 * tx + j], 0.f);

    __syncthreads();

    // write Y1 row-major [node][feat] (float4, conflict-minimal) + reload W2
    #pragma unroll
    for (int i = 0; i < 4; i++) {
        float4 v = make_float4(y[i][0], y[i][1], y[i][2], y[i][3]);
        *(float4*)(Zt + (4 * ty + i) * PAD + 4 * tx) = v;
    }
    for (int i = tid; i < 4096; i += 256) Ws[i] = W2p[i];
    __syncthreads();

    // ---- GEMM2: O = Y1 @ W2 + b2 ----
    #pragma unroll
    for (int i = 0; i < 4; i++)
        #pragma unroll
        for (int j = 0; j < 4; j++) acc[i][j] = 0.f;

    #pragma unroll 8
    for (int k = 0; k < 64; k++) {
        float4 b = *(const float4*)(Ws + k * 64 + 4 * tx);
        float a0 = Zt[(4 * ty + 0) * PAD + k];
        float a1 = Zt[(4 * ty + 1) * PAD + k];
        float a2 = Zt[(4 * ty + 2) * PAD + k];
        float a3 = Zt[(4 * ty + 3) * PAD + k];
        acc[0][0] += a0 * b.x; acc[0][1] += a0 * b.y; acc[0][2] += a0 * b.z; acc[0][3] += a0 * b.w;
        acc[1][0] += a1 * b.x; acc[1][1] += a1 * b.y; acc[1][2] += a1 * b.z; acc[1][3] += a1 * b.w;
        acc[2][0] += a2 * b.x; acc[2][1] += a2 * b.y; acc[2][2] += a2 * b.z; acc[2][3] += a2 * b.w;
        acc[3][0] += a3 * b.x; acc[3][1] += a3 * b.y; acc[3][2] += a3 * b.z; acc[3][3] += a3 * b.w;
    }

    // ---- epilogue: bias, optional BN(eval)+ReLU, store ----
    #pragma unroll
    for (int i = 0; i < 4; i++) {
        int n = base + 4 * ty + i;
        if (n < NN) {
            float4 o;
            o.x = acc[i][0] + bias2[4 * tx + 0];
            o.y = acc[i][1] + bias2[4 * tx + 1];
            o.z = acc[i][2] + bias2[4 * tx + 2];
            o.w = acc[i][3] + bias2[4 * tx + 3];
            if (layer < 4) {
                o.x = fmaxf(o.x * bnsc[4 * tx + 0] + bnsh[4 * tx + 0], 0.f);
                o.y = fmaxf(o.y * bnsc[4 * tx + 1] + bnsh[4 * tx + 1], 0.f);
                o.z = fmaxf(o.z * bnsc[4 * tx + 2] + bnsh[4 * tx + 2], 0.f);
                o.w = fmaxf(o.w * bnsc[4 * tx + 3] + bnsh[4 * tx + 3], 0.f);
            }
            *(float4*)(hout + n * 64 + 4 * tx) = o;
        }
    }
}

// ---------------- launch ----------------
extern "C" void kernel_launch(void* const* d_in, const int* in_sizes, int n_in,
                              void* d_out, int out_size) {
    const float* x   = (const float*)d_in[0];
    const int*   ei  = (const int*)d_in[1];     // [2, E] int32 (JAX x64 disabled)
    const float* W1  = (const float*)d_in[2];
    const float* b1  = (const float*)d_in[3];
    const float* W2  = (const float*)d_in[4];
    const float* b2  = (const float*)d_in[5];
    const float* bng = (const float*)d_in[6];
    const float* bnb = (const float*)d_in[7];
    const float* bnm = (const float*)d_in[8];
    const float* bnv = (const float*)d_in[9];
    float* out = (float*)d_out;

    const int gN = (NN + 255) / 256;     // 391
    const int gE = (EE + 255) / 256;     // 6250

    // CSR build (deterministic segment order via per-node sort)
    k_zero_deg<<<gN, 256>>>();
    k_hist<<<gE, 256>>>(ei);
    k_scan1<<<NB_SCAN, 1024>>>();
    k_scan2<<<1, 1>>>();
    k_scanadd<<<gN, 256>>>();
    k_scatter<<<gE, 256>>>(ei);
    k_segsort<<<gN, 256>>>();

    // 5 fused layers (ping-pong buffers resolved inside the kernel)
    const int gL = (NN + 63) / 64;       // 1563
    for (int layer = 0; layer < 5; layer++) {
        k_layer<<<gL, 256>>>(x, out, W1, b1, W2, b2, bng, bnb, bnm, bnv, layer);
    }
}